// round 5
// baseline (speedup 1.0000x reference)
#include <cuda_runtime.h>
#include <cuda_fp16.h>
#include <cstdint>

#define TOKENS 64
#define NFEAT  8192
#define KFEAT  8192
#define ROWB   32768                  // bytes per weight row / per g_xe row
#define KSPLIT 4
#define KB_CTA (ROWB / KSPLIT)        // 8192 bytes (2048 codes) per CTA
#define CTA_N  256
#define CHUNKB 128                    // K bytes per iter (32 codes)
#define NITER  (KB_CTA / CHUNKB)      // 64
#define NSTAGE 4

#define B_BYTES (CTA_N * CHUNKB)      // 32768
#define A_BYTES (TOKENS * CHUNKB)     // 8192
#define STAGE_BYTES (B_BYTES + A_BYTES)   // 40960
#define A_SUB   B_BYTES
#define SMEM_TOTAL (NSTAGE * STAGE_BYTES) // 163840

#define SW128(o) ((o) ^ (((o) >> 3) & 0x70))

__device__ __align__(16) uint8_t g_xe[(size_t)TOKENS * ROWB];           // 2MB {fp16(x),0} words
__device__ float g_sumx4[TOKENS * 4];
__device__ __align__(16) float g_part[KSPLIT][(size_t)TOKENS * NFEAT];  // 8MB

// ---------------------------------------------------------------------------
__device__ __forceinline__ uint32_t smem_u32(const void* p) {
    uint32_t a;
    asm("{ .reg .u64 t; cvta.to.shared.u64 t, %1; cvt.u32.u64 %0, t; }" : "=r"(a) : "l"(p));
    return a;
}
__device__ __forceinline__ void cpa16(uint32_t dst, const void* src) {
    asm volatile("cp.async.cg.shared.global [%0], [%1], 16;\n" :: "r"(dst), "l"(src));
}
#define CP_COMMIT() asm volatile("cp.async.commit_group;\n" ::: "memory")
#define CP_WAIT2()  asm volatile("cp.async.wait_group 2;\n" ::: "memory")

#define LDSM4(R0, R1, R2, R3, addr)                                            \
    asm volatile("ldmatrix.sync.aligned.m8n8.x4.shared.b16 {%0,%1,%2,%3}, [%4];" \
        : "=r"(R0), "=r"(R1), "=r"(R2), "=r"(R3) : "r"(addr))

__device__ __forceinline__ void mma16816(float* d, const uint32_t* a, uint32_t b0, uint32_t b1) {
    asm volatile(
        "mma.sync.aligned.m16n8k16.row.col.f32.f16.f16.f32 "
        "{%0,%1,%2,%3},{%4,%5,%6,%7},{%8,%9},{%0,%1,%2,%3};"
        : "+f"(d[0]), "+f"(d[1]), "+f"(d[2]), "+f"(d[3])
        : "r"(a[0]), "r"(a[1]), "r"(a[2]), "r"(a[3]), "r"(b0), "r"(b1));
}

// ---------------------------------------------------------------------------
// Prep: x fp32 -> {fp16(x),0} uint32 words in g_xe; partial sums of x16.
// grid (64 tokens, 4 quarters), 256 threads: 2 float4 per thread.
// ---------------------------------------------------------------------------
__global__ __launch_bounds__(256) void prep_kernel(const float* __restrict__ x) {
    __shared__ float red[256];
    const int t = blockIdx.x, qtr = blockIdx.y, tid = threadIdx.x;
    const float4* xr = reinterpret_cast<const float4*>(x + (size_t)t * KFEAT) + qtr * 512;
    uint4* dst = reinterpret_cast<uint4*>(g_xe + (size_t)t * ROWB) + qtr * 512;
    float sm = 0.f;
#pragma unroll
    for (int i = 0; i < 2; i++) {
        float4 v = xr[tid + 256 * i];
        __half h0 = __float2half_rn(v.x), h1 = __float2half_rn(v.y);
        __half h2 = __float2half_rn(v.z), h3 = __float2half_rn(v.w);
        sm += (__half2float(h0) + __half2float(h1)) + (__half2float(h2) + __half2float(h3));
        dst[tid + 256 * i] = make_uint4((uint32_t)__half_as_ushort(h0),
                                        (uint32_t)__half_as_ushort(h1),
                                        (uint32_t)__half_as_ushort(h2),
                                        (uint32_t)__half_as_ushort(h3));
    }
    red[tid] = sm; __syncthreads();
    for (int s = 128; s > 0; s >>= 1) { if (tid < s) red[tid] += red[tid + s]; __syncthreads(); }
    if (tid == 0) g_sumx4[t * 4 + qtr] = red[0];
}

// ---------------------------------------------------------------------------
// GEMM: 64tok x 256outch x 2048codes per CTA. B raw bytes = fp16 subnormals.
// acc = sum_k x16 * (c * 2^-24); stored raw to g_part[split].
// ---------------------------------------------------------------------------
__global__ __launch_bounds__(256, 1) void gemm_kernel(const uint8_t* __restrict__ q) {
    extern __shared__ __align__(1024) uint8_t smem[];
    const int tid  = threadIdx.x;
    const int lane = tid & 31;
    const int warp = tid >> 5;
    const uint32_t sbase = smem_u32(smem);

    const int blockN = blockIdx.x * CTA_N;
    const size_t kbB = (size_t)blockIdx.y * KB_CTA;

    const uint8_t* bsrc = q + (size_t)(blockN + tid) * ROWB + kbB;   // one B row per thread
    // A: 512 segs of 16B; thread covers segs {tid, tid+256}
    const int s0 = tid, s1 = tid + 256;
    const uint8_t* as0 = g_xe + (size_t)(s0 >> 3) * ROWB + kbB + (s0 & 7) * 16;
    const uint8_t* as1 = g_xe + (size_t)(s1 >> 3) * ROWB + kbB + (s1 & 7) * 16;
    const uint32_t ad0 = SW128((uint32_t)(s0 * 16));
    const uint32_t ad1 = SW128((uint32_t)(s1 * 16));

#define LOAD_CHUNK(c) do {                                                      \
    uint32_t st_ = sbase + (uint32_t)((c) & (NSTAGE - 1)) * STAGE_BYTES;        \
    const uint8_t* bs_ = bsrc + (size_t)(c) * CHUNKB;                           \
    _Pragma("unroll")                                                           \
    for (int seg = 0; seg < 8; seg++)                                           \
        cpa16(st_ + SW128((uint32_t)(tid * 128 + seg * 16)), bs_ + seg * 16);   \
    cpa16(st_ + A_SUB + ad0, as0 + (size_t)(c) * CHUNKB);                       \
    cpa16(st_ + A_SUB + ad1, as1 + (size_t)(c) * CHUNKB);                       \
    CP_COMMIT();                                                                \
} while (0)

    // prologue: chunks 0..2 in flight
    LOAD_CHUNK(0); LOAD_CHUNK(1); LOAD_CHUNK(2);

    const int m0 = (warp & 1) * 32;
    const int n0 = (warp >> 1) * 64;
    const int rl = lane & 15;
    const int kh = (lane >> 4) * 16;

    float acc[2][8][4];
#pragma unroll
    for (int mi = 0; mi < 2; mi++)
#pragma unroll
        for (int nf = 0; nf < 8; nf++)
#pragma unroll
            for (int j = 0; j < 4; j++) acc[mi][nf][j] = 0.f;

    for (int i = 0; i < NITER; i++) {
        CP_WAIT2();
        __syncthreads();

        if (i + 3 < NITER) LOAD_CHUNK(i + 3); else CP_COMMIT();

        const uint32_t stg = sbase + (uint32_t)(i & (NSTAGE - 1)) * STAGE_BYTES;
        const uint32_t bB = stg;
        const uint32_t aB = stg + A_SUB;

#pragma unroll
        for (int kk = 0; kk < 4; kk++) {
            const uint32_t colb = (uint32_t)(kk * 32 + kh);
            uint32_t a[2][4];
#pragma unroll
            for (int mi = 0; mi < 2; mi++)
                LDSM4(a[mi][0], a[mi][1], a[mi][2], a[mi][3],
                      aB + SW128((uint32_t)((m0 + mi * 16 + rl) * 128) + colb));
#pragma unroll
            for (int bg = 0; bg < 4; bg++) {
                uint32_t r0, r1, r2, r3;
                LDSM4(r0, r1, r2, r3,
                      bB + SW128((uint32_t)((n0 + bg * 16 + rl) * 128) + colb));
#pragma unroll
                for (int mi = 0; mi < 2; mi++) {
                    mma16816(acc[mi][bg * 2 + 0], a[mi], r0, r2);
                    mma16816(acc[mi][bg * 2 + 1], a[mi], r1, r3);
                }
            }
        }
    }

    // epilogue: raw partial dot products
    float* pp = &g_part[blockIdx.y][0];
#pragma unroll
    for (int mi = 0; mi < 2; mi++)
#pragma unroll
        for (int nf = 0; nf < 8; nf++) {
            int col = blockN + n0 + (nf >> 1) * 16 + (nf & 1) * 8 + (lane & 3) * 2;
            int t0  = m0 + mi * 16 + (lane >> 2);
            *reinterpret_cast<float2*>(&pp[(size_t)t0 * NFEAT + col]) =
                make_float2(acc[mi][nf][0], acc[mi][nf][1]);
            *reinterpret_cast<float2*>(&pp[(size_t)(t0 + 8) * NFEAT + col]) =
                make_float2(acc[mi][nf][2], acc[mi][nf][3]);
        }
#undef LOAD_CHUNK
}

// ---------------------------------------------------------------------------
// Reduce: y = s * (2^24 * sum_splits - zp * sumx_t) + bias
// ---------------------------------------------------------------------------
__global__ void reduce_kernel(const float* __restrict__ scales,
                              const int* __restrict__ zp,
                              const float* __restrict__ bias,
                              float* __restrict__ out) {
    int i = blockIdx.x * blockDim.x + threadIdx.x;     // float4 units
    int col4 = i & (NFEAT / 4 - 1);
    int t    = i >> 11;
    float4 a = reinterpret_cast<const float4*>(g_part[0])[i];
    float4 b = reinterpret_cast<const float4*>(g_part[1])[i];
    float4 c = reinterpret_cast<const float4*>(g_part[2])[i];
    float4 d = reinterpret_cast<const float4*>(g_part[3])[i];
    float4 sc = reinterpret_cast<const float4*>(scales)[col4];
    float4 bi = reinterpret_cast<const float4*>(bias)[col4];
    int4   zi = reinterpret_cast<const int4*>(zp)[col4];
    float sx = (g_sumx4[t * 4 + 0] + g_sumx4[t * 4 + 1]) +
               (g_sumx4[t * 4 + 2] + g_sumx4[t * 4 + 3]);
    const float SC = 16777216.0f;  // 2^24
    float4 r;
    r.x = bi.x + sc.x * (SC * ((a.x + b.x) + (c.x + d.x)) - (float)zi.x * sx);
    r.y = bi.y + sc.y * (SC * ((a.y + b.y) + (c.y + d.y)) - (float)zi.y * sx);
    r.z = bi.z + sc.z * (SC * ((a.z + b.z) + (c.z + d.z)) - (float)zi.z * sx);
    r.w = bi.w + sc.w * (SC * ((a.w + b.w) + (c.w + d.w)) - (float)zi.w * sx);
    reinterpret_cast<float4*>(out)[i] = r;
}

// ---------------------------------------------------------------------------
extern "C" void kernel_launch(void* const* d_in, const int* in_sizes, int n_in,
                              void* d_out, int out_size) {
    const float* x    = (const float*)d_in[0];
    const int*   qw   = (const int*)d_in[1];
    const float* sc   = (const float*)d_in[2];
    const int*   zp   = (const int*)d_in[3];
    const float* bias = (const float*)d_in[4];
    float*       out  = (float*)d_out;
    (void)in_sizes; (void)n_in; (void)out_size;

    static int configured = 0;
    cudaFuncSetAttribute(gemm_kernel, cudaFuncAttributeMaxDynamicSharedMemorySize, SMEM_TOTAL);
    (void)configured;

    prep_kernel<<<dim3(TOKENS, 4), 256>>>(x);
    gemm_kernel<<<dim3(NFEAT / CTA_N, KSPLIT), 256, SMEM_TOTAL>>>((const uint8_t*)qw);
    reduce_kernel<<<(TOKENS * NFEAT / 4) / 256, 256>>>(sc, zp, bias, out);
}

// round 6
// speedup vs baseline: 2.0570x; 2.0570x over previous
#include <cuda_runtime.h>
#include <cuda_fp16.h>
#include <cstdint>

#define TOKENS   64
#define NFEAT    8192
#define KFEAT    8192

#define KSPLIT    4
#define K_PER_CTA (KFEAT / KSPLIT)      // 2048 codes
#define CTA_N     128                   // 8 warps x 16 channels
#define ITER_C    32                    // codes per iteration
#define NITER     (K_PER_CTA / ITER_C)  // 64
#define PITCH     40                    // halves per smem A row (80B, conflict-free)
#define ASTAGES   4

// scratch
__device__ __align__(16) __half g_x16[TOKENS * KFEAT];            // 1MB, K-permuted fp16 x
__device__ float g_sumx[TOKENS];
__device__ __align__(16) float g_part[KSPLIT][TOKENS * NFEAT];    // 8MB

// ---------------------------------------------------------------------------
// Prep: write x16 with per-16-group permutation sigma(j)=((j>>3)&1)*2+(j&1)+((j>>1)&3)*4
// so that B's natural-order LDG.128 lands on the right fragment slots.
// ---------------------------------------------------------------------------
__global__ __launch_bounds__(256) void prep_kernel(const float* __restrict__ x) {
    __shared__ float red[256];
    const int t = blockIdx.x, tid = threadIdx.x;
    const float* xr = x + (size_t)t * KFEAT;
    float sm = 0.f;
#pragma unroll
    for (int gi = 0; gi < 2; gi++) {
        int g = tid + gi * 256;                      // 16-code group index
        float v[16];
#pragma unroll
        for (int i = 0; i < 4; i++) {
            float4 f = reinterpret_cast<const float4*>(xr + g * 16)[i];
            v[i * 4 + 0] = f.x; v[i * 4 + 1] = f.y; v[i * 4 + 2] = f.z; v[i * 4 + 3] = f.w;
        }
        unsigned short w[16];
#pragma unroll
        for (int j = 0; j < 16; j++) {
            int s = ((j >> 3) & 1) * 2 + (j & 1) + ((j >> 1) & 3) * 4;
            __half h = __float2half_rn(v[s]);
            sm += __half2float(h);
            w[j] = __half_as_ushort(h);
        }
        uint4* dst = reinterpret_cast<uint4*>(g_x16 + (size_t)t * KFEAT + g * 16);
        dst[0] = make_uint4((uint32_t)w[0] | ((uint32_t)w[1] << 16),
                            (uint32_t)w[2] | ((uint32_t)w[3] << 16),
                            (uint32_t)w[4] | ((uint32_t)w[5] << 16),
                            (uint32_t)w[6] | ((uint32_t)w[7] << 16));
        dst[1] = make_uint4((uint32_t)w[8] | ((uint32_t)w[9] << 16),
                            (uint32_t)w[10] | ((uint32_t)w[11] << 16),
                            (uint32_t)w[12] | ((uint32_t)w[13] << 16),
                            (uint32_t)w[14] | ((uint32_t)w[15] << 16));
    }
    red[tid] = sm; __syncthreads();
    for (int s = 128; s > 0; s >>= 1) { if (tid < s) red[tid] += red[tid + s]; __syncthreads(); }
    if (tid == 0) g_sumx[t] = red[0];
}

// ---------------------------------------------------------------------------
__device__ __forceinline__ void cpa16(uint32_t dst, const void* src) {
    asm volatile("cp.async.ca.shared.global [%0], [%1], 16;\n" :: "r"(dst), "l"(src));
}
#define CP_COMMIT() asm volatile("cp.async.commit_group;\n" ::: "memory")
#define CP_WAIT2()  asm volatile("cp.async.wait_group 2;\n" ::: "memory")

// [a.b0, 0, b.b0, 0] -> half2 {ca*2^-24, cb*2^-24} (exact), one PRMT.
__device__ __forceinline__ uint32_t pack2(uint32_t a, uint32_t b) {
    uint32_t r;
    asm("prmt.b32 %0, %1, %2, 0x5410;" : "=r"(r) : "r"(a), "r"(b));
    return r;
}
__device__ __forceinline__ void mma16816(float* d, const uint32_t* a, uint32_t b0, uint32_t b1) {
    asm volatile(
        "mma.sync.aligned.m16n8k16.row.col.f32.f16.f16.f32 "
        "{%0,%1,%2,%3},{%4,%5,%6,%7},{%8,%9},{%0,%1,%2,%3};"
        : "+f"(d[0]), "+f"(d[1]), "+f"(d[2]), "+f"(d[3])
        : "r"(a[0]), "r"(a[1]), "r"(a[2]), "r"(a[3]), "r"(b0), "r"(b1));
}

// ---------------------------------------------------------------------------
// GEMM: 64tok x 128ch x 2048codes per CTA; 256 CTAs, 2/SM.
// acc = sum_k x16_perm * (c * 2^-24), raw to g_part[split].
// ---------------------------------------------------------------------------
__global__ __launch_bounds__(256, 2) void gemm_kernel(const int* __restrict__ q) {
    __shared__ __align__(16) __half sA[ASTAGES][TOKENS * PITCH];   // 4 x 5120 B

    const int tid  = threadIdx.x;
    const int warp = tid >> 5;
    const int lane = tid & 31;

    const int n0 = blockIdx.x * CTA_N + warp * 16;
    const int kb = blockIdx.y * K_PER_CTA;

    const int r0 = n0 + (lane >> 2);
    const int r1 = r0 + 8;
    const int qd4 = (lane & 3) * 4;

    const int* pB0 = q + (size_t)r0 * KFEAT + kb + qd4;
    const int* pB1 = q + (size_t)r1 * KFEAT + kb + qd4;

    // A staging: 64 rows x 32 halves (64B) per iter; 256 thr x 16B
    const int arow = tid >> 2;
    const int aseg = tid & 3;
    const __half* asrc = g_x16 + (size_t)arow * KFEAT + kb + aseg * 8;
    const uint32_t sbase = (uint32_t)__cvta_generic_to_shared(&sA[0][0]);
    const uint32_t ABUF  = TOKENS * PITCH * 2;
    const uint32_t adst  = (uint32_t)(arow * PITCH + aseg * 8) * 2;

    // B register prefetch, 2 iters deep: raw[parity][nf][s]
    int4 raw[2][2][2];
#pragma unroll
    for (int i = 0; i < 2; i++) {
#pragma unroll
        for (int s = 0; s < 2; s++) {
            raw[i][0][s] = __ldcs((const int4*)(pB0 + i * ITER_C + s * 16));
            raw[i][1][s] = __ldcs((const int4*)(pB1 + i * ITER_C + s * 16));
        }
    }
    // A cp.async prologue: iters 0,1,2
#pragma unroll
    for (int i = 0; i < 3; i++) {
        cpa16(sbase + i * ABUF + adst, asrc + i * ITER_C);
        CP_COMMIT();
    }

    float acc[4][2][4];
#pragma unroll
    for (int mi = 0; mi < 4; mi++)
#pragma unroll
        for (int nf = 0; nf < 2; nf++)
#pragma unroll
            for (int j = 0; j < 4; j++) acc[mi][nf][j] = 0.f;

    const int rl = lane & 15;
    const int kh = (lane >> 4) * 8;

    for (int i = 0; i < NITER; i++) {
        CP_WAIT2();
        __syncthreads();

        // A for iter i+3
        if (i + 3 < NITER) {
            cpa16(sbase + ((i + 3) & 3) * ABUF + adst, asrc + (size_t)(i + 3) * ITER_C);
            CP_COMMIT();
        } else {
            CP_COMMIT();
        }

        // convert this iter's raw codes (1 PRMT per half2)
        uint32_t bf[2][2][2];   // [nf][s][reg]
#pragma unroll
        for (int nf = 0; nf < 2; nf++)
#pragma unroll
            for (int s = 0; s < 2; s++) {
                int4 w = raw[i & 1][nf][s];
                bf[nf][s][0] = pack2((uint32_t)w.x, (uint32_t)w.y);
                bf[nf][s][1] = pack2((uint32_t)w.z, (uint32_t)w.w);
            }

        // prefetch iter i+2 into the freed parity slot
        if (i + 2 < NITER) {
            const int off = (i + 2) * ITER_C;
#pragma unroll
            for (int s = 0; s < 2; s++) {
                raw[i & 1][0][s] = __ldcs((const int4*)(pB0 + off + s * 16));
                raw[i & 1][1][s] = __ldcs((const int4*)(pB1 + off + s * 16));
            }
        }

        // compute: 2 k16 steps x 4 m-tiles x 2 n-frags
        const uint32_t abase = sbase + (uint32_t)(i & 3) * ABUF;
#pragma unroll
        for (int s = 0; s < 2; s++) {
            uint32_t a[4][4];
#pragma unroll
            for (int mi = 0; mi < 4; mi++) {
                uint32_t addr = abase + (uint32_t)((mi * 16 + rl) * PITCH + s * 16 + kh) * 2;
                asm volatile(
                    "ldmatrix.sync.aligned.m8n8.x4.shared.b16 {%0,%1,%2,%3}, [%4];"
                    : "=r"(a[mi][0]), "=r"(a[mi][1]), "=r"(a[mi][2]), "=r"(a[mi][3])
                    : "r"(addr));
            }
#pragma unroll
            for (int mi = 0; mi < 4; mi++)
#pragma unroll
                for (int nf = 0; nf < 2; nf++)
                    mma16816(acc[mi][nf], a[mi], bf[nf][s][0], bf[nf][s][1]);
        }
    }

    // epilogue: raw partial dots
    float* pp = &g_part[blockIdx.y][0];
    const int kc2 = (lane & 3) * 2;
#pragma unroll
    for (int mi = 0; mi < 4; mi++)
#pragma unroll
        for (int nf = 0; nf < 2; nf++) {
            int col = n0 + nf * 8 + kc2;
            int t0  = mi * 16 + (lane >> 2);
            *reinterpret_cast<float2*>(&pp[(size_t)t0 * NFEAT + col]) =
                make_float2(acc[mi][nf][0], acc[mi][nf][1]);
            *reinterpret_cast<float2*>(&pp[(size_t)(t0 + 8) * NFEAT + col]) =
                make_float2(acc[mi][nf][2], acc[mi][nf][3]);
        }
}

// ---------------------------------------------------------------------------
// Reduce: y = s * (2^24 * sum_splits - zp * sumx_t) + bias
// ---------------------------------------------------------------------------
__global__ void reduce_kernel(const float* __restrict__ scales,
                              const int* __restrict__ zp,
                              const float* __restrict__ bias,
                              float* __restrict__ out) {
    int i = blockIdx.x * blockDim.x + threadIdx.x;     // float4 units
    int col4 = i & (NFEAT / 4 - 1);
    int t    = i >> 11;
    float4 a = reinterpret_cast<const float4*>(g_part[0])[i];
    float4 b = reinterpret_cast<const float4*>(g_part[1])[i];
    float4 c = reinterpret_cast<const float4*>(g_part[2])[i];
    float4 d = reinterpret_cast<const float4*>(g_part[3])[i];
    float4 sc = reinterpret_cast<const float4*>(scales)[col4];
    float4 bi = reinterpret_cast<const float4*>(bias)[col4];
    int4   zi = reinterpret_cast<const int4*>(zp)[col4];
    float sx = g_sumx[t];
    const float SC = 16777216.0f;  // 2^24
    float4 r;
    r.x = bi.x + sc.x * (SC * ((a.x + b.x) + (c.x + d.x)) - (float)zi.x * sx);
    r.y = bi.y + sc.y * (SC * ((a.y + b.y) + (c.y + d.y)) - (float)zi.y * sx);
    r.z = bi.z + sc.z * (SC * ((a.z + b.z) + (c.z + d.z)) - (float)zi.z * sx);
    r.w = bi.w + sc.w * (SC * ((a.w + b.w) + (c.w + d.w)) - (float)zi.w * sx);
    reinterpret_cast<float4*>(out)[i] = r;
}

// ---------------------------------------------------------------------------
extern "C" void kernel_launch(void* const* d_in, const int* in_sizes, int n_in,
                              void* d_out, int out_size) {
    const float* x    = (const float*)d_in[0];
    const int*   qw   = (const int*)d_in[1];
    const float* sc   = (const float*)d_in[2];
    const int*   zp   = (const int*)d_in[3];
    const float* bias = (const float*)d_in[4];
    float*       out  = (float*)d_out;
    (void)in_sizes; (void)n_in; (void)out_size;

    prep_kernel<<<TOKENS, 256>>>(x);
    gemm_kernel<<<dim3(NFEAT / CTA_N, KSPLIT), 256>>>(qw);
    reduce_kernel<<<(TOKENS * NFEAT / 4) / 256, 256>>>(sc, zp, bias, out);
}